// round 17
// baseline (speedup 1.0000x reference)
#include <cuda_runtime.h>
#include <cuda_bf16.h>
#include <cuda_fp16.h>
#include <cstdint>

#define Bc 4
#define Cc 256
#define Nn 4096

__device__ __nv_bfloat16 g_Qbh[(size_t)Bc*Nn*32];
__device__ __nv_bfloat16 g_Qbl[(size_t)Bc*Nn*32];
__device__ __nv_bfloat16 g_Kbh[(size_t)Bc*Nn*32];
__device__ __nv_bfloat16 g_Kbl[(size_t)Bc*Nn*32];
__device__ __half g_Vh[(size_t)Bc*Cc*Nn];   // [b][c][n], fp16

// bf16 m16n8k16
__device__ __forceinline__ void mma16b(float d[4], const uint32_t a[4], const uint32_t b[2]){
    asm volatile("mma.sync.aligned.m16n8k16.row.col.f32.bf16.bf16.f32 "
        "{%0,%1,%2,%3}, {%4,%5,%6,%7}, {%8,%9}, {%0,%1,%2,%3};"
        : "+f"(d[0]), "+f"(d[1]), "+f"(d[2]), "+f"(d[3])
        : "r"(a[0]), "r"(a[1]), "r"(a[2]), "r"(a[3]), "r"(b[0]), "r"(b[1]));
}
// fp16 m16n8k16
__device__ __forceinline__ void mma16f(float d[4], const uint32_t a[4], const uint32_t b[2]){
    asm volatile("mma.sync.aligned.m16n8k16.row.col.f32.f16.f16.f32 "
        "{%0,%1,%2,%3}, {%4,%5,%6,%7}, {%8,%9}, {%0,%1,%2,%3};"
        : "+f"(d[0]), "+f"(d[1]), "+f"(d[2]), "+f"(d[3])
        : "r"(a[0]), "r"(a[1]), "r"(a[2]), "r"(a[3]), "r"(b[0]), "r"(b[1]));
}
#define LDSM4(r, a) \
    asm volatile("ldmatrix.sync.aligned.m8n8.x4.shared.b16 {%0,%1,%2,%3}, [%4];" \
        : "=r"((r)[0]), "=r"((r)[1]), "=r"((r)[2]), "=r"((r)[3]) : "r"(a))
#define LDSM2T(r, a) \
    asm volatile("ldmatrix.sync.aligned.m8n8.x2.trans.shared.b16 {%0,%1}, [%2];" \
        : "=r"((r)[0]), "=r"((r)[1]) : "r"(a))

__device__ __forceinline__ uint32_t smaddr(const void* p){
    return (uint32_t)__cvta_generic_to_shared(p);
}
__device__ __forceinline__ uint32_t bfpk(__nv_bfloat16 a, __nv_bfloat16 b){
    unsigned short ua = *(unsigned short*)&a, ub = *(unsigned short*)&b;
    return (uint32_t)ua | ((uint32_t)ub << 16);
}

// ---------------------------------------------------------------------------
// Kernel 1: proj GEMM on tensor cores (bf16 3-pass split).
// CTA: 64 out-rows x 128 cols, K=256 resident. grid (32, 5, 4), 256 thr.
// smem u32 offsets: Wh 64x132, Wl, Xh 256x68, Xl.  Total 206848 B.
#define PW_STRIDE 132
#define PX_STRIDE 68
#define P_WL (64*132)
#define P_XH (2*64*132)
#define P_XL (2*64*132 + 256*68)
#define PS_BYTES ((2*64*132 + 2*256*68)*4)
// ---------------------------------------------------------------------------
__global__ void __launch_bounds__(256, 1)
proj_kernel(const float* __restrict__ x,
            const float* __restrict__ Wq, const float* __restrict__ bq,
            const float* __restrict__ Wk, const float* __restrict__ bk,
            const float* __restrict__ Wv, const float* __restrict__ bv)
{
    extern __shared__ uint32_t ps[];
    const int t = threadIdx.x, w = t >> 5, lane = t & 31;
    const int g = lane >> 2, m = lane & 3;
    const int n0 = blockIdx.x * 128, o0 = blockIdx.y * 64, b = blockIdx.z;
    const int rbw = w & 3, cbw = w >> 2;

    // ---- stage W (hi/lo bf16), rows 64 x k 256 ----
    #pragma unroll
    for (int it = 0; it < 16; it++) {
        int fi = t + it*256, row = fi >> 6, k4 = fi & 63;
        int o = o0 + row;
        const float* src = (o < 32) ? Wq + o*256 : (o < 64) ? Wk + (o-32)*256 : Wv + (o-64)*256;
        float4 v = *(const float4*)(src + k4*4);
        __nv_bfloat16 hx = __float2bfloat16(v.x), hy = __float2bfloat16(v.y);
        __nv_bfloat16 hz = __float2bfloat16(v.z), hw = __float2bfloat16(v.w);
        ps[row*PW_STRIDE + k4*2]     = bfpk(hx, hy);
        ps[row*PW_STRIDE + k4*2 + 1] = bfpk(hz, hw);
        ps[P_WL + row*PW_STRIDE + k4*2]     = bfpk(__float2bfloat16(v.x - __bfloat162float(hx)),
                                                   __float2bfloat16(v.y - __bfloat162float(hy)));
        ps[P_WL + row*PW_STRIDE + k4*2 + 1] = bfpk(__float2bfloat16(v.z - __bfloat162float(hz)),
                                                   __float2bfloat16(v.w - __bfloat162float(hw)));
    }
    // ---- stage X (hi/lo bf16), [k 256][n 128] ----
    #pragma unroll
    for (int it = 0; it < 32; it++) {
        int fi = t + it*256, k = fi >> 5, n4 = fi & 31;
        float4 v = *(const float4*)(x + ((size_t)(b*Cc + k))*Nn + n0 + n4*4);
        __nv_bfloat16 hx = __float2bfloat16(v.x), hy = __float2bfloat16(v.y);
        __nv_bfloat16 hz = __float2bfloat16(v.z), hw = __float2bfloat16(v.w);
        ps[P_XH + k*PX_STRIDE + n4*2]     = bfpk(hx, hy);
        ps[P_XH + k*PX_STRIDE + n4*2 + 1] = bfpk(hz, hw);
        ps[P_XL + k*PX_STRIDE + n4*2]     = bfpk(__float2bfloat16(v.x - __bfloat162float(hx)),
                                                 __float2bfloat16(v.y - __bfloat162float(hy)));
        ps[P_XL + k*PX_STRIDE + n4*2 + 1] = bfpk(__float2bfloat16(v.z - __bfloat162float(hz)),
                                                 __float2bfloat16(v.w - __bfloat162float(hw)));
    }
    __syncthreads();

    float oacc[8][4];
    #pragma unroll
    for (int nb = 0; nb < 8; nb++)
        #pragma unroll
        for (int i = 0; i < 4; i++) oacc[nb][i] = 0.f;

    // ldmatrix lane addresses
    const uint32_t base = smaddr(ps);
    const uint32_t whA = base + (uint32_t)((rbw*16 + (lane & 15))*PW_STRIDE*4 + (lane >> 4)*16);
    const uint32_t wlA = whA + P_WL*4;
    const uint32_t xhB = base + (uint32_t)(P_XH*4 + (lane & 15)*PX_STRIDE*4 + cbw*128);
    const uint32_t xlB = xhB + (uint32_t)((P_XL - P_XH)*4);

    #pragma unroll 4
    for (int ks = 0; ks < 16; ks++) {
        uint32_t ah[4], al[4];
        LDSM4(ah, whA + ks*32);
        LDSM4(al, wlA + ks*32);
        const uint32_t bks = (uint32_t)(ks*16*PX_STRIDE*4);
        #pragma unroll
        for (int nb = 0; nb < 8; nb++) {
            uint32_t bh[2], bl[2];
            LDSM2T(bh, xhB + bks + nb*16);
            LDSM2T(bl, xlB + bks + nb*16);
            mma16b(oacc[nb], ah, bh);
            mma16b(oacc[nb], ah, bl);
            mma16b(oacc[nb], al, bh);
        }
    }

    // ---- epilogue ----
    const int r0 = o0 + rbw*16 + g, r1 = r0 + 8;
    const int cb0 = n0 + cbw*64 + 2*m;
    if (blockIdx.y == 0) {
        const bool isQ = (rbw < 2);
        const int od0 = r0 & 31, od1 = r1 & 31;
        __nv_bfloat16* hi = isQ ? g_Qbh : g_Kbh;
        __nv_bfloat16* lo = isQ ? g_Qbl : g_Kbl;
        const float bs0 = isQ ? bq[od0] : bk[od0];
        const float bs1 = isQ ? bq[od1] : bk[od1];
        #pragma unroll
        for (int nb = 0; nb < 8; nb++) {
            int c = cb0 + nb*8;
            float v00 = oacc[nb][0] + bs0, v01 = oacc[nb][1] + bs0;
            float v10 = oacc[nb][2] + bs1, v11 = oacc[nb][3] + bs1;
            __nv_bfloat16 h;
            h = __float2bfloat16(v00);
            hi[((size_t)b*Nn + c)*32 + od0] = h;
            lo[((size_t)b*Nn + c)*32 + od0] = __float2bfloat16(v00 - __bfloat162float(h));
            h = __float2bfloat16(v01);
            hi[((size_t)b*Nn + c + 1)*32 + od0] = h;
            lo[((size_t)b*Nn + c + 1)*32 + od0] = __float2bfloat16(v01 - __bfloat162float(h));
            h = __float2bfloat16(v10);
            hi[((size_t)b*Nn + c)*32 + od1] = h;
            lo[((size_t)b*Nn + c)*32 + od1] = __float2bfloat16(v10 - __bfloat162float(h));
            h = __float2bfloat16(v11);
            hi[((size_t)b*Nn + c + 1)*32 + od1] = h;
            lo[((size_t)b*Nn + c + 1)*32 + od1] = __float2bfloat16(v11 - __bfloat162float(h));
        }
    } else {
        const int od0 = r0 - 64, od1 = r1 - 64;
        const float bs0 = bv[od0], bs1 = bv[od1];
        #pragma unroll
        for (int nb = 0; nb < 8; nb++) {
            int c = cb0 + nb*8;
            __half2 p0 = __floats2half2_rn(oacc[nb][0] + bs0, oacc[nb][1] + bs0);
            __half2 p1 = __floats2half2_rn(oacc[nb][2] + bs1, oacc[nb][3] + bs1);
            *(__half2*)(g_Vh + ((size_t)(b*Cc + od0))*Nn + c) = p0;
            *(__half2*)(g_Vh + ((size_t)(b*Cc + od1))*Nn + c) = p1;
        }
    }
}

// ---------------------------------------------------------------------------
// Kernel 2: flash attention (online softmax). grid (32, 4), 256 threads.
// (unchanged from the 260.5us R16 kernel)
#define KH_B   0
#define KL_B   5120
#define V_B    10240
#define P_B    83968
#define LS_B   102400
#define SCS_B  102912
#define SM_BYTES 103424
// ---------------------------------------------------------------------------
__global__ void __launch_bounds__(256, 1)
attn_kernel(const float* __restrict__ x, float* __restrict__ out)
{
    extern __shared__ char smc[];
    uint32_t* smu = (uint32_t*)smc;
    uint32_t* P32 = (uint32_t*)(smc + P_B);
    float*    LS  = (float*)(smc + LS_B);
    float*    SCS = (float*)(smc + SCS_B);
    const int t = threadIdx.x, w = t >> 5, lane = t & 31;
    const int g = lane >> 2, m = lane & 3;
    const int b = blockIdx.y, QI0 = blockIdx.x * 128;
    const int rs = w * 16;
    const int rowg = (w & 1) * 64, colg = (w >> 1) * 64;
    const __half* gV = g_Vh + (size_t)b*Cc*Nn;

    uint32_t qh[2][4], ql[2][4];
    #pragma unroll
    for (int ks = 0; ks < 2; ks++)
        #pragma unroll
        for (int i = 0; i < 4; i++) {
            size_t row = (size_t)b*Nn + QI0 + rs + g + (i&1)*8;
            int d = ks*16 + 2*m + (i>>1)*8;
            qh[ks][i] = *(const uint32_t*)(g_Qbh + row*32 + d);
            ql[ks][i] = *(const uint32_t*)(g_Qbl + row*32 + d);
        }

    float o[4][8][4];
    #pragma unroll
    for (int rb = 0; rb < 4; rb++)
        #pragma unroll
        for (int cb = 0; cb < 8; cb++)
            #pragma unroll
            for (int i = 0; i < 4; i++) o[rb][cb][i] = 0.f;
    float lsum0 = 0.f, lsum1 = 0.f;
    float m0 = -1e30f, m1 = -1e30f;

    {
        int j = t >> 2, q4 = t & 3;
        const uint4* sh = (const uint4*)(g_Kbh + ((size_t)b*Nn + j)*32);
        const uint4* sl = (const uint4*)(g_Kbl + ((size_t)b*Nn + j)*32);
        *(uint4*)(smu + j*20 + q4*4)        = sh[q4];
        *(uint4*)(smu + 1280 + j*20 + q4*4) = sl[q4];
    }
    {
        uint32_t* V0 = (uint32_t*)(smc + V_B);
        #pragma unroll
        for (int it = 0; it < 8; it++) {
            int f = t + it*256, c = f >> 3, ch = f & 7;
            uint4 v = *(const uint4*)(gV + (size_t)c*Nn + ch*8);
            *(uint4*)(V0 + c*36 + ch*4) = v;
        }
    }
    __syncthreads();

    for (int tt = 0; tt < 64; tt++) {
        uint32_t* V32 = (uint32_t*)(smc + V_B + (tt & 1)*36864);
        float s[8][4];
        #pragma unroll
        for (int nb = 0; nb < 8; nb++) {
            #pragma unroll
            for (int i = 0; i < 4; i++) s[nb][i] = 0.f;
            #pragma unroll
            for (int ks = 0; ks < 2; ks++) {
                const uint32_t* kh = smu + (nb*8 + g)*20 + ks*8 + m;
                const uint32_t* kl = smu + 1280 + (nb*8 + g)*20 + ks*8 + m;
                uint32_t bh[2] = { kh[0], kh[4] };
                uint32_t bl[2] = { kl[0], kl[4] };
                mma16b(s[nb], qh[ks], bh);
                mma16b(s[nb], qh[ks], bl);
                mma16b(s[nb], ql[ks], bh);
            }
        }
        float t0 = -1e30f, t1 = -1e30f;
        #pragma unroll
        for (int nb = 0; nb < 8; nb++) {
            t0 = fmaxf(t0, fmaxf(s[nb][0], s[nb][1]));
            t1 = fmaxf(t1, fmaxf(s[nb][2], s[nb][3]));
        }
        t0 = fmaxf(t0, __shfl_xor_sync(0xffffffffu, t0, 1));
        t0 = fmaxf(t0, __shfl_xor_sync(0xffffffffu, t0, 2));
        t1 = fmaxf(t1, __shfl_xor_sync(0xffffffffu, t1, 1));
        t1 = fmaxf(t1, __shfl_xor_sync(0xffffffffu, t1, 2));
        float mn0 = fmaxf(m0, t0), mn1 = fmaxf(m1, t1);
        float sc0 = __expf(m0 - mn0), sc1 = __expf(m1 - mn1);
        m0 = mn0; m1 = mn1;
        float ps0 = 0.f, ps1 = 0.f;
        #pragma unroll
        for (int nb = 0; nb < 8; nb++) {
            float p0 = __expf(s[nb][0] - mn0), p1 = __expf(s[nb][1] - mn0);
            float p2 = __expf(s[nb][2] - mn1), p3 = __expf(s[nb][3] - mn1);
            ps0 += p0 + p1;  ps1 += p2 + p3;
            __half2 h01 = __floats2half2_rn(p0, p1);
            __half2 h23 = __floats2half2_rn(p2, p3);
            P32[(rs + g)*36 + nb*4 + m]     = *(uint32_t*)&h01;
            P32[(rs + g + 8)*36 + nb*4 + m] = *(uint32_t*)&h23;
        }
        lsum0 = lsum0*sc0 + ps0;
        lsum1 = lsum1*sc1 + ps1;
        if (m == 0) { SCS[rs + g] = sc0; SCS[rs + g + 8] = sc1; }
        __syncthreads();

        #pragma unroll
        for (int rb = 0; rb < 4; rb++) {
            float sa = SCS[rowg + rb*16 + g];
            float sb = SCS[rowg + rb*16 + g + 8];
            #pragma unroll
            for (int cb = 0; cb < 8; cb++) {
                o[rb][cb][0] *= sa; o[rb][cb][1] *= sa;
                o[rb][cb][2] *= sb; o[rb][cb][3] *= sb;
            }
        }
        #pragma unroll
        for (int ks = 0; ks < 4; ks++) {
            uint32_t a[4][4];
            #pragma unroll
            for (int rb = 0; rb < 4; rb++) {
                int R0 = (rowg + rb*16 + g)*36 + ks*8 + m;
                int R1 = (rowg + rb*16 + g + 8)*36 + ks*8 + m;
                a[rb][0] = P32[R0];     a[rb][1] = P32[R1];
                a[rb][2] = P32[R0 + 4]; a[rb][3] = P32[R1 + 4];
            }
            #pragma unroll
            for (int cb = 0; cb < 8; cb++) {
                int C = (colg + cb*8 + g)*36 + ks*8 + m;
                uint32_t bb[2] = { V32[C], V32[C + 4] };
                #pragma unroll
                for (int rb = 0; rb < 4; rb++) mma16f(o[rb][cb], a[rb], bb);
            }
        }
        if (tt < 63) {
            int j0 = (tt + 1) * 64;
            {
                int j = t >> 2, q4 = t & 3;
                const uint4* sh = (const uint4*)(g_Kbh + ((size_t)b*Nn + j0 + j)*32);
                const uint4* sl = (const uint4*)(g_Kbl + ((size_t)b*Nn + j0 + j)*32);
                *(uint4*)(smu + j*20 + q4*4)        = sh[q4];
                *(uint4*)(smu + 1280 + j*20 + q4*4) = sl[q4];
            }
            uint32_t* Vn = (uint32_t*)(smc + V_B + ((tt + 1) & 1)*36864);
            #pragma unroll
            for (int it = 0; it < 8; it++) {
                int f = t + it*256, c = f >> 3, ch = f & 7;
                uint4 v = *(const uint4*)(gV + (size_t)c*Nn + j0 + ch*8);
                *(uint4*)(Vn + c*36 + ch*4) = v;
            }
        }
        __syncthreads();
    }

    lsum0 += __shfl_xor_sync(0xffffffffu, lsum0, 1);
    lsum0 += __shfl_xor_sync(0xffffffffu, lsum0, 2);
    lsum1 += __shfl_xor_sync(0xffffffffu, lsum1, 1);
    lsum1 += __shfl_xor_sync(0xffffffffu, lsum1, 2);
    if (m == 0) { LS[rs + g] = lsum0; LS[rs + g + 8] = lsum1; }

    float* Os = (float*)smc;
    const float* xb = x   + (size_t)b*Cc*Nn + QI0;
    float*       ob = out + (size_t)b*Cc*Nn + QI0;
    const int r4 = (t & 31) * 4, c0 = t >> 5;
    #pragma unroll
    for (int h2 = 0; h2 < 2; h2++) {
        __syncthreads();
        if ((colg >> 7) == h2) {
            #pragma unroll
            for (int rb = 0; rb < 4; rb++) {
                int r0 = rowg + rb*16 + g;
                float iv0 = 1.0f / LS[r0];
                float iv1 = 1.0f / LS[r0 + 8];
                #pragma unroll
                for (int cb = 0; cb < 8; cb++) {
                    int c = (colg & 127) + cb*8 + 2*m;
                    Os[(c    )*132 + r0    ] = o[rb][cb][0] * iv0;
                    Os[(c + 1)*132 + r0    ] = o[rb][cb][1] * iv0;
                    Os[(c    )*132 + r0 + 8] = o[rb][cb][2] * iv1;
                    Os[(c + 1)*132 + r0 + 8] = o[rb][cb][3] * iv1;
                }
            }
        }
        __syncthreads();
        #pragma unroll 4
        for (int k = 0; k < 16; k++) {
            int c = k*8 + c0;
            size_t gi = (size_t)(h2*128 + c)*Nn + r4;
            float4 ov = *(const float4*)(Os + c*132 + r4);
            float4 xv = *(const float4*)(xb + gi);
            ov.x += xv.x; ov.y += xv.y; ov.z += xv.z; ov.w += xv.w;
            *(float4*)(ob + gi) = ov;
        }
    }
}

// ---------------------------------------------------------------------------
extern "C" void kernel_launch(void* const* d_in, const int* in_sizes, int n_in,
                              void* d_out, int out_size)
{
    const float* x  = (const float*)d_in[0];
    const float* Wq = (const float*)d_in[1];
    const float* bq = (const float*)d_in[2];
    const float* Wk = (const float*)d_in[3];
    const float* bk = (const float*)d_in[4];
    const float* Wv = (const float*)d_in[5];
    const float* bv = (const float*)d_in[6];
    float* out = (float*)d_out;

    cudaFuncSetAttribute(proj_kernel, cudaFuncAttributeMaxDynamicSharedMemorySize, PS_BYTES);
    cudaFuncSetAttribute(attn_kernel, cudaFuncAttributeMaxDynamicSharedMemorySize, SM_BYTES);
    proj_kernel<<<dim3(Nn/128, 5, Bc), 256, PS_BYTES>>>(x, Wq, bq, Wk, bk, Wv, bv);
    attn_kernel<<<dim3(Nn/128, Bc), 256, SM_BYTES>>>(x, out);
}